// round 14
// baseline (speedup 1.0000x reference)
#include <cuda_runtime.h>
#include <cuda_bf16.h>
#include <stdint.h>

// GCN 3-layer: n=50000 nodes, E=800000 edges (+self loops), 64->64->64->16.
// Factorized normalization: out[dst] = dinv[dst] * (hs[dst] + sum_src hs[src]),
// hs = (x@W)*dinv. Aggregation via on-device CSR (grouped by dst) GATHER.
// R12 passed at 142.8us; this round cuts launches 14->10 and removes the
// esrc/edst round-trip. GEMM + gather kernels are byte-identical to the pass.
//
// edge_index dtype (int32 vs int64) detected at runtime (odd-word sampling).

#define MAX_N 50048
#define MAX_E 800000

__device__ int   g_nz32;                // nonzero odd word seen => int32 layout
__device__ int   g_cnt     [MAX_N];     // in-degree (excl self-loop)
__device__ int   g_rowstart[MAX_N];     // CSR row offsets
__device__ int   g_cursor  [MAX_N];     // fill cursors
__device__ float g_dinv    [MAX_N];
__device__ int   g_srcs    [MAX_E];     // src ids grouped by dst
__device__ __align__(16) float g_hs [MAX_N * 64];
__device__ __align__(16) float g_agg[MAX_N * 64];
__device__ __align__(16) float g_hs3[MAX_N * 16];

// ---------------------------------------------------------------------------
// k_prep: zero g_cnt (all blocks) + dtype detection (block 0, smem-local flag,
// single writer to g_nz32 -- no cross-block reset race).
// ---------------------------------------------------------------------------
__global__ void k_prep(const int* __restrict__ ei32, int n) {
    int i = blockIdx.x * blockDim.x + threadIdx.x;
    if (i < n) g_cnt[i] = 0;
    if (blockIdx.x == 0) {
        __shared__ int flag;
        if (threadIdx.x == 0) flag = 0;
        __syncthreads();
        for (int k = threadIdx.x; k < 2048; k += blockDim.x)
            if (ei32[2 * k + 1] != 0) atomicOr(&flag, 1);
        __syncthreads();
        if (threadIdx.x == 0) g_nz32 = flag;
    }
}

// ---------------------------------------------------------------------------
// k_hist: degree histogram straight from the edge buffer (layout-branched).
// ---------------------------------------------------------------------------
__global__ void k_hist(const int* __restrict__ ei32, int E) {
    int e = blockIdx.x * blockDim.x + threadIdx.x;
    if (e >= E) return;
    int d = g_nz32 ? ei32[E + e] : ei32[2 * E + 2 * e];
    atomicAdd(&g_cnt[d], 1);
}

// ---------------------------------------------------------------------------
// k_scan: single-block 1024-thread exclusive scan of g_cnt (deterministic).
// Each thread owns a contiguous chunk; smem scan of the 1024 partials; then
// per-thread prefix writes rowstart/cursor/dinv.
// ---------------------------------------------------------------------------
__global__ __launch_bounds__(1024) void k_scan(int n) {
    __shared__ int sh[1024];
    int chunk = (n + 1023) / 1024;
    int t = threadIdx.x;
    int lo = t * chunk;
    int hi = min(lo + chunk, n);
    int sum = 0;
    for (int i = lo; i < hi; i++) sum += g_cnt[i];
    sh[t] = sum;
    __syncthreads();
    for (int off = 1; off < 1024; off <<= 1) {
        int v = (t >= off) ? sh[t - off] : 0;
        __syncthreads();
        sh[t] += v;
        __syncthreads();
    }
    int run = sh[t] - sum;                    // exclusive base for this chunk
    for (int i = lo; i < hi; i++) {
        int c = g_cnt[i];
        g_rowstart[i] = run;
        g_cursor[i]   = run;
        g_dinv[i]     = rsqrtf(1.0f + (float)c);   // +1 = self-loop
        run += c;
    }
}

// ---------------------------------------------------------------------------
// k_fill: scatter src ids into dst-grouped CSR (layout-branched edge reads).
// ---------------------------------------------------------------------------
__global__ void k_fill(const int* __restrict__ ei32, int E) {
    int e = blockIdx.x * blockDim.x + threadIdx.x;
    if (e >= E) return;
    int s, d;
    if (g_nz32) {               // int32 layout: [src x E][dst x E]
        s = ei32[e];
        d = ei32[E + e];
    } else {                    // int64 layout: low words at even positions
        s = ei32[2 * e];
        d = ei32[2 * E + 2 * e];
    }
    int pos = atomicAdd(&g_cursor[d], 1);
    g_srcs[pos] = s;
}

// ---------------------------------------------------------------------------
// GEMM: one output row per thread, W in shared.  (unchanged from the pass)
//   GIN:  input = g_agg instead of `in`
//   PRE:  v = relu(v*dinv[row] + b_prev[k])  on the input row
//   L3:   write g_hs3 (16-wide) instead of g_hs
//   epilogue: hs[row] = (row @ W) * dinv[row]
// ---------------------------------------------------------------------------
template<int IN, int OUT, bool PRE, bool GIN, bool L3>
__global__ __launch_bounds__(128)
void k_gemm(const float* __restrict__ in, const float* __restrict__ W,
            const float* __restrict__ b_prev, int n)
{
    __shared__ float Ws[IN * OUT];
    __shared__ float bs[IN];
    for (int i = threadIdx.x; i < IN * OUT; i += 128) Ws[i] = W[i];
    if (PRE) {
        for (int i = threadIdx.x; i < IN; i += 128) bs[i] = b_prev[i];
    }
    __syncthreads();

    int row = blockIdx.x * 128 + threadIdx.x;
    if (row >= n) return;
    float dv = g_dinv[row];

    float acc[OUT];
#pragma unroll
    for (int j = 0; j < OUT; j++) acc[j] = 0.0f;

    const float* ip = (GIN ? (const float*)g_agg : in) + (size_t)row * IN;
#pragma unroll
    for (int k = 0; k < IN; k += 4) {
        float4 v = *reinterpret_cast<const float4*>(ip + k);
        if (PRE) {
            v.x = fmaxf(fmaf(v.x, dv, bs[k + 0]), 0.0f);
            v.y = fmaxf(fmaf(v.y, dv, bs[k + 1]), 0.0f);
            v.z = fmaxf(fmaf(v.z, dv, bs[k + 2]), 0.0f);
            v.w = fmaxf(fmaf(v.w, dv, bs[k + 3]), 0.0f);
        }
        float xk[4] = {v.x, v.y, v.z, v.w};
#pragma unroll
        for (int kk = 0; kk < 4; kk++) {
            float xv = xk[kk];
            const float* wrow = &Ws[(k + kk) * OUT];
#pragma unroll
            for (int j = 0; j < OUT; j += 4) {
                float4 w = *reinterpret_cast<const float4*>(wrow + j);
                acc[j + 0] = fmaf(xv, w.x, acc[j + 0]);
                acc[j + 1] = fmaf(xv, w.y, acc[j + 1]);
                acc[j + 2] = fmaf(xv, w.z, acc[j + 2]);
                acc[j + 3] = fmaf(xv, w.w, acc[j + 3]);
            }
        }
    }

    float* hp = (L3 ? g_hs3 : g_hs) + (size_t)row * OUT;
#pragma unroll
    for (int j = 0; j < OUT; j += 4) {
        float4 o;
        o.x = acc[j + 0] * dv;
        o.y = acc[j + 1] * dv;
        o.z = acc[j + 2] * dv;
        o.w = acc[j + 3] * dv;
        *reinterpret_cast<float4*>(hp + j) = o;
    }
}

// ---------------------------------------------------------------------------
// CSR gather aggregation (unchanged from the pass):
// agg[row] = hs[row] + sum_{s in nbrs(row)} hs[s].  F/4 lanes per node.
//   FIN: write out[row] = acc*dinv[row] + b3 instead of g_agg.
// ---------------------------------------------------------------------------
template<int F, bool L3, bool FIN>
__global__ void k_aggr(const float* __restrict__ b3, float* __restrict__ out, int n)
{
    constexpr int LPG = F / 4;
    int t = blockIdx.x * blockDim.x + threadIdx.x;
    int row = t / LPG;
    int lane = t % LPG;
    if (row >= n) return;

    const float4* hs4 = reinterpret_cast<const float4*>(L3 ? g_hs3 : g_hs);

    float4 acc = __ldg(hs4 + (size_t)row * LPG + lane);      // self-loop
    int j = g_rowstart[row];
    int end = j + g_cnt[row];

    for (; j + 4 <= end; j += 4) {
        int s0 = g_srcs[j + 0];
        int s1 = g_srcs[j + 1];
        int s2 = g_srcs[j + 2];
        int s3 = g_srcs[j + 3];
        float4 v0 = __ldg(hs4 + (size_t)s0 * LPG + lane);
        float4 v1 = __ldg(hs4 + (size_t)s1 * LPG + lane);
        float4 v2 = __ldg(hs4 + (size_t)s2 * LPG + lane);
        float4 v3 = __ldg(hs4 + (size_t)s3 * LPG + lane);
        acc.x += v0.x + v1.x + v2.x + v3.x;
        acc.y += v0.y + v1.y + v2.y + v3.y;
        acc.z += v0.z + v1.z + v2.z + v3.z;
        acc.w += v0.w + v1.w + v2.w + v3.w;
    }
    for (; j < end; j++) {
        int s = g_srcs[j];
        float4 v = __ldg(hs4 + (size_t)s * LPG + lane);
        acc.x += v.x; acc.y += v.y; acc.z += v.z; acc.w += v.w;
    }

    if (FIN) {
        float dv = g_dinv[row];
        float4 o;
        o.x = fmaf(acc.x, dv, b3[lane * 4 + 0]);
        o.y = fmaf(acc.y, dv, b3[lane * 4 + 1]);
        o.z = fmaf(acc.z, dv, b3[lane * 4 + 2]);
        o.w = fmaf(acc.w, dv, b3[lane * 4 + 3]);
        reinterpret_cast<float4*>(out)[(size_t)row * LPG + lane] = o;
    } else {
        reinterpret_cast<float4*>(g_agg)[(size_t)row * LPG + lane] = acc;
    }
}

// ---------------------------------------------------------------------------
extern "C" void kernel_launch(void* const* d_in, const int* in_sizes, int n_in,
                              void* d_out, int out_size)
{
    const float* x    = (const float*)d_in[0];
    const int*   ei32 = (const int*)d_in[1];   // [2,E], int32 OR int64 (detected)
    const float* W1 = (const float*)d_in[2];
    const float* b1 = (const float*)d_in[3];
    const float* W2 = (const float*)d_in[4];
    const float* b2 = (const float*)d_in[5];
    const float* W3 = (const float*)d_in[6];
    const float* b3 = (const float*)d_in[7];
    float* out = (float*)d_out;

    int n = in_sizes[0] / 64;       // 50000
    int E = in_sizes[1] / 2;        // 800000

    const int T = 256;
    int nb = (n + T - 1) / T;

    // CSR build: 4 launches (was 8)
    k_prep<<<nb, T>>>(ei32, n);
    k_hist<<<(E + T - 1) / T, T>>>(ei32, E);
    k_scan<<<1, 1024>>>(n);
    k_fill<<<(E + T - 1) / T, T>>>(ei32, E);

    int gemm_blocks = (n + 127) / 128;
    int ab64 = (int)(((long long)n * 16 + T - 1) / T);
    int ab16 = (int)(((long long)n * 4  + T - 1) / T);

    // Layer 1
    k_gemm<64, 64, false, false, false><<<gemm_blocks, 128>>>(x, W1, nullptr, n);
    k_aggr<64, false, false><<<ab64, T>>>(nullptr, nullptr, n);

    // Layer 2 (input = relu(agg*dinv + b1))
    k_gemm<64, 64, true, true, false><<<gemm_blocks, 128>>>(nullptr, W2, b1, n);
    k_aggr<64, false, false><<<ab64, T>>>(nullptr, nullptr, n);

    // Layer 3 (64 -> 16), aggregation fused with final epilogue
    k_gemm<64, 16, true, true, true><<<gemm_blocks, 128>>>(nullptr, W3, b2, n);
    k_aggr<16, true, true><<<ab16, T>>>(b3, out, n);
}

// round 16
// speedup vs baseline: 1.6758x; 1.6758x over previous
#include <cuda_runtime.h>
#include <cuda_bf16.h>
#include <stdint.h>

// GCN 3-layer: n=50000 nodes, E=800000 edges (+self loops), 64->64->64->16.
// Factorized normalization: out[dst] = dinv[dst] * (hs[dst] + sum_src hs[src]),
// hs = (x@W)*dinv. Aggregation via on-device CSR (grouped by dst) GATHER.
//
// R12 passed at 142.8us. R14's fusion experiment regressed to 223us
// (single-block scan + strided direct edge reads). This is R12 restored,
// keeping ONLY the safe prep fusion (flag_init+detect+zero -> k_prep).

#define MAX_N 50048
#define MAX_E 800000
#define NB_MAX 256

__device__ int   g_nz32;                // nonzero odd word seen => int32 layout
__device__ int   g_cnt     [MAX_N];     // in-degree (excl self-loop)
__device__ int   g_rowstart[MAX_N];     // CSR row offsets
__device__ int   g_cursor  [MAX_N];     // fill cursors
__device__ float g_dinv    [MAX_N];
__device__ int   g_bsum    [NB_MAX];
__device__ int   g_boff    [NB_MAX];
__device__ int   g_esrc    [MAX_E];     // unpacked edge src (coalesced 4B)
__device__ int   g_edst    [MAX_E];     // unpacked edge dst (coalesced 4B)
__device__ int   g_srcs    [MAX_E];     // src ids grouped by dst
__device__ __align__(16) float g_hs [MAX_N * 64];
__device__ __align__(16) float g_agg[MAX_N * 64];
__device__ __align__(16) float g_hs3[MAX_N * 16];

// ---------------------------------------------------------------------------
// k_prep: zero g_cnt (all blocks) + dtype detection (block 0, smem-local flag,
// single writer to g_nz32 -- no cross-block reset race).
// ---------------------------------------------------------------------------
__global__ void k_prep(const int* __restrict__ ei32, int n) {
    int i = blockIdx.x * blockDim.x + threadIdx.x;
    if (i < n) g_cnt[i] = 0;
    if (blockIdx.x == 0) {
        __shared__ int flag;
        if (threadIdx.x == 0) flag = 0;
        __syncthreads();
        for (int k = threadIdx.x; k < 2048; k += blockDim.x)
            if (ei32[2 * k + 1] != 0) atomicOr(&flag, 1);
        __syncthreads();
        if (threadIdx.x == 0) g_nz32 = flag;
    }
}

// ---------------------------------------------------------------------------
// k_pack: unpack edges to coalesced int32 arrays + degree histogram.
// (Identical role to R12's k_pack, which measured 11.6us.)
// ---------------------------------------------------------------------------
__global__ void k_pack(const int* __restrict__ ei32, int E) {
    int e = blockIdx.x * blockDim.x + threadIdx.x;
    if (e >= E) return;
    int s, d;
    if (g_nz32) {               // int32 layout: [src x E][dst x E]
        s = ei32[e];
        d = ei32[E + e];
    } else {                    // int64 layout: low words at even positions
        s = ei32[2 * e];
        d = ei32[2 * E + 2 * e];
    }
    g_esrc[e] = s;
    g_edst[e] = d;
    atomicAdd(&g_cnt[d], 1);
}

// ---------------------------------------------------------------------------
// CSR scan (two-level, 196 parallel blocks -- the R12 version) + fill
// ---------------------------------------------------------------------------
__global__ void k_scan1(int n) {              // per-block total
    __shared__ int sh[256];
    int i = blockIdx.x * 256 + threadIdx.x;
    sh[threadIdx.x] = (i < n) ? g_cnt[i] : 0;
    __syncthreads();
    for (int off = 128; off > 0; off >>= 1) {
        if (threadIdx.x < off) sh[threadIdx.x] += sh[threadIdx.x + off];
        __syncthreads();
    }
    if (threadIdx.x == 0) g_bsum[blockIdx.x] = sh[0];
}

__global__ void k_scan2(int nb) {             // exclusive scan of block sums
    if (threadIdx.x == 0 && blockIdx.x == 0) {
        int run = 0;
        for (int b = 0; b < nb; b++) { int t = g_bsum[b]; g_boff[b] = run; run += t; }
    }
}

__global__ void k_scan3(int n) {              // element offsets + dinv
    __shared__ int sh[256];
    int i = blockIdx.x * 256 + threadIdx.x;
    int c = (i < n) ? g_cnt[i] : 0;
    sh[threadIdx.x] = c;
    __syncthreads();
    for (int off = 1; off < 256; off <<= 1) {
        int v = (threadIdx.x >= off) ? sh[threadIdx.x - off] : 0;
        __syncthreads();
        sh[threadIdx.x] += v;
        __syncthreads();
    }
    if (i < n) {
        int rs = g_boff[blockIdx.x] + sh[threadIdx.x] - c;   // exclusive
        g_rowstart[i] = rs;
        g_cursor[i]   = rs;
        g_dinv[i]     = rsqrtf(1.0f + (float)c);             // +1 = self-loop
    }
}

__global__ void k_fill(int E) {
    int e = blockIdx.x * blockDim.x + threadIdx.x;
    if (e < E) {
        int pos = atomicAdd(&g_cursor[g_edst[e]], 1);
        g_srcs[pos] = g_esrc[e];
    }
}

// ---------------------------------------------------------------------------
// GEMM: one output row per thread, W in shared.  (byte-identical to the pass)
// ---------------------------------------------------------------------------
template<int IN, int OUT, bool PRE, bool GIN, bool L3>
__global__ __launch_bounds__(128)
void k_gemm(const float* __restrict__ in, const float* __restrict__ W,
            const float* __restrict__ b_prev, int n)
{
    __shared__ float Ws[IN * OUT];
    __shared__ float bs[IN];
    for (int i = threadIdx.x; i < IN * OUT; i += 128) Ws[i] = W[i];
    if (PRE) {
        for (int i = threadIdx.x; i < IN; i += 128) bs[i] = b_prev[i];
    }
    __syncthreads();

    int row = blockIdx.x * 128 + threadIdx.x;
    if (row >= n) return;
    float dv = g_dinv[row];

    float acc[OUT];
#pragma unroll
    for (int j = 0; j < OUT; j++) acc[j] = 0.0f;

    const float* ip = (GIN ? (const float*)g_agg : in) + (size_t)row * IN;
#pragma unroll
    for (int k = 0; k < IN; k += 4) {
        float4 v = *reinterpret_cast<const float4*>(ip + k);
        if (PRE) {
            v.x = fmaxf(fmaf(v.x, dv, bs[k + 0]), 0.0f);
            v.y = fmaxf(fmaf(v.y, dv, bs[k + 1]), 0.0f);
            v.z = fmaxf(fmaf(v.z, dv, bs[k + 2]), 0.0f);
            v.w = fmaxf(fmaf(v.w, dv, bs[k + 3]), 0.0f);
        }
        float xk[4] = {v.x, v.y, v.z, v.w};
#pragma unroll
        for (int kk = 0; kk < 4; kk++) {
            float xv = xk[kk];
            const float* wrow = &Ws[(k + kk) * OUT];
#pragma unroll
            for (int j = 0; j < OUT; j += 4) {
                float4 w = *reinterpret_cast<const float4*>(wrow + j);
                acc[j + 0] = fmaf(xv, w.x, acc[j + 0]);
                acc[j + 1] = fmaf(xv, w.y, acc[j + 1]);
                acc[j + 2] = fmaf(xv, w.z, acc[j + 2]);
                acc[j + 3] = fmaf(xv, w.w, acc[j + 3]);
            }
        }
    }

    float* hp = (L3 ? g_hs3 : g_hs) + (size_t)row * OUT;
#pragma unroll
    for (int j = 0; j < OUT; j += 4) {
        float4 o;
        o.x = acc[j + 0] * dv;
        o.y = acc[j + 1] * dv;
        o.z = acc[j + 2] * dv;
        o.w = acc[j + 3] * dv;
        *reinterpret_cast<float4*>(hp + j) = o;
    }
}

// ---------------------------------------------------------------------------
// CSR gather aggregation (byte-identical to the pass).
// ---------------------------------------------------------------------------
template<int F, bool L3, bool FIN>
__global__ void k_aggr(const float* __restrict__ b3, float* __restrict__ out, int n)
{
    constexpr int LPG = F / 4;
    int t = blockIdx.x * blockDim.x + threadIdx.x;
    int row = t / LPG;
    int lane = t % LPG;
    if (row >= n) return;

    const float4* hs4 = reinterpret_cast<const float4*>(L3 ? g_hs3 : g_hs);

    float4 acc = __ldg(hs4 + (size_t)row * LPG + lane);      // self-loop
    int j = g_rowstart[row];
    int end = j + g_cnt[row];

    for (; j + 4 <= end; j += 4) {
        int s0 = g_srcs[j + 0];
        int s1 = g_srcs[j + 1];
        int s2 = g_srcs[j + 2];
        int s3 = g_srcs[j + 3];
        float4 v0 = __ldg(hs4 + (size_t)s0 * LPG + lane);
        float4 v1 = __ldg(hs4 + (size_t)s1 * LPG + lane);
        float4 v2 = __ldg(hs4 + (size_t)s2 * LPG + lane);
        float4 v3 = __ldg(hs4 + (size_t)s3 * LPG + lane);
        acc.x += v0.x + v1.x + v2.x + v3.x;
        acc.y += v0.y + v1.y + v2.y + v3.y;
        acc.z += v0.z + v1.z + v2.z + v3.z;
        acc.w += v0.w + v1.w + v2.w + v3.w;
    }
    for (; j < end; j++) {
        int s = g_srcs[j];
        float4 v = __ldg(hs4 + (size_t)s * LPG + lane);
        acc.x += v.x; acc.y += v.y; acc.z += v.z; acc.w += v.w;
    }

    if (FIN) {
        float dv = g_dinv[row];
        float4 o;
        o.x = fmaf(acc.x, dv, b3[lane * 4 + 0]);
        o.y = fmaf(acc.y, dv, b3[lane * 4 + 1]);
        o.z = fmaf(acc.z, dv, b3[lane * 4 + 2]);
        o.w = fmaf(acc.w, dv, b3[lane * 4 + 3]);
        reinterpret_cast<float4*>(out)[(size_t)row * LPG + lane] = o;
    } else {
        reinterpret_cast<float4*>(g_agg)[(size_t)row * LPG + lane] = acc;
    }
}

// ---------------------------------------------------------------------------
extern "C" void kernel_launch(void* const* d_in, const int* in_sizes, int n_in,
                              void* d_out, int out_size)
{
    const float* x    = (const float*)d_in[0];
    const int*   ei32 = (const int*)d_in[1];   // [2,E], int32 OR int64 (detected)
    const float* W1 = (const float*)d_in[2];
    const float* b1 = (const float*)d_in[3];
    const float* W2 = (const float*)d_in[4];
    const float* b2 = (const float*)d_in[5];
    const float* W3 = (const float*)d_in[6];
    const float* b3 = (const float*)d_in[7];
    float* out = (float*)d_out;

    int n = in_sizes[0] / 64;       // 50000
    int E = in_sizes[1] / 2;        // 800000

    const int T = 256;
    int nb = (n + 255) / 256;       // scan blocks (196)

    // CSR build (R12 structure; prep fusion only)
    k_prep <<<nb, T>>>(ei32, n);
    k_pack <<<(E + T - 1) / T, T>>>(ei32, E);
    k_scan1<<<nb, T>>>(n);
    k_scan2<<<1, 32>>>(nb);
    k_scan3<<<nb, T>>>(n);
    k_fill <<<(E + T - 1) / T, T>>>(E);

    int gemm_blocks = (n + 127) / 128;
    int ab64 = (int)(((long long)n * 16 + T - 1) / T);
    int ab16 = (int)(((long long)n * 4  + T - 1) / T);

    // Layer 1
    k_gemm<64, 64, false, false, false><<<gemm_blocks, 128>>>(x, W1, nullptr, n);
    k_aggr<64, false, false><<<ab64, T>>>(nullptr, nullptr, n);

    // Layer 2 (input = relu(agg*dinv + b1))
    k_gemm<64, 64, true, true, false><<<gemm_blocks, 128>>>(nullptr, W2, b1, n);
    k_aggr<64, false, false><<<ab64, T>>>(nullptr, nullptr, n);

    // Layer 3 (64 -> 16), aggregation fused with final epilogue
    k_gemm<64, 16, true, true, true><<<gemm_blocks, 128>>>(nullptr, W3, b2, n);
    k_aggr<16, true, true><<<ab16, T>>>(b3, out, n);
}